// round 8
// baseline (speedup 1.0000x reference)
#include <cuda_runtime.h>
#include <cuda_fp16.h>
#include <cstdint>

#define NNODES 20000
#define NEDGES 320000
#define NEPLUS 340000   // edges + self loops
#define NGRAPH 256
#define VOCAB  128
#define NWH    294912   // fp16 weights: W2(65536) lw2(65536) W3(131072) lw3(32768)

// ---------------- scratch (device globals; no runtime alloc allowed) ----------------
__device__ float  g_feat [2][NNODES * 128];  // layer-3 output (fp32, pooled)
__device__ __half g_feath[2][NNODES * 256];  // concat-layer outputs (GEMM inputs)
__device__ __half g_xh   [2][NNODES * 512];  // fp16 message features
__device__ float  g_lin  [2][NNODES * 256];
__device__ float  g_as   [2][NNODES * 4];
__device__ float  g_ad   [2][NNODES * 4];
__device__ int    g_off  [2][NNODES + 1];
__device__ int    g_cur  [2][NNODES];
__device__ int    g_srcs [2][NEPLUS];
__device__ int    g_gcnt [2][NGRAPH];
__device__ int    g_bsum [2][128];
__device__ float  g_tab  [VOCAB * 512];
__device__ float  g_tatt [VOCAB * 8];
__device__ __half g_wh   [NWH];

__device__ __forceinline__ float lrelu(float x) { return x > 0.f ? x : 0.2f * x; }

__device__ __forceinline__ float pick4(float4 v, int h) {
    float r = v.x;
    r = (h == 1) ? v.y : r;
    r = (h == 2) ? v.z : r;
    r = (h == 3) ? v.w : r;
    return r;
}

__device__ __forceinline__ uint32_t sptr(const void* p) {
    return (uint32_t)__cvta_generic_to_shared(p);
}
#define CPA(dst, src, sz) \
    asm volatile("cp.async.cg.shared.global [%0], [%1], 16, %2;" :: "r"(dst), "l"(src), "r"(sz))
#define CP_COMMIT() asm volatile("cp.async.commit_group;" ::: "memory")
#define CP_WAIT1()  asm volatile("cp.async.wait_group 1;" ::: "memory")
#define CP_WAIT0()  asm volatile("cp.async.wait_group 0;" ::: "memory")

// ---------------- weight fp32->fp16 conversion ----------------
__global__ void k_wconv(const float* __restrict__ W2, const float* __restrict__ lw2,
                        const float* __restrict__ W3, const float* __restrict__ lw3) {
    int i = blockIdx.x * blockDim.x + threadIdx.x;
    if (i >= NWH) return;
    float v;
    if (i < 65536)       v = W2[i];
    else if (i < 131072) v = lw2[i - 65536];
    else if (i < 262144) v = W3[i - 131072];
    else                 v = lw3[i - 262144];
    g_wh[i] = __float2half_rn(v);
}

// ---------------- layer-1 precompute: tables over the 128-entry vocab ----------------
__global__ void k_pre(const float* __restrict__ emb, const float* __restrict__ W1,
                      const float* __restrict__ lw1, const float* __restrict__ as1,
                      const float* __restrict__ ad1) {
    __shared__ float er[128];
    __shared__ float sAs[4], sAd[4];
    int v = blockIdx.x, t = threadIdx.x;  // 256 threads
    if (t < 128) er[t] = emb[v * 128 + t];
    if (t < 4) { sAs[t] = 0.f; sAd[t] = 0.f; }
    __syncthreads();
    float acc0 = 0.f, acc1 = 0.f;
    for (int k = 0; k < 128; k++) {
        float e = er[k];
        acc0 += e * W1[k * 256 + t];
        acc1 += e * lw1[k * 256 + t];
    }
    g_tab[v * 512 + t] = acc0;
    g_tab[v * 512 + 256 + t] = acc1;
    int h = t >> 6, c = t & 63;
    atomicAdd(&sAs[h], acc0 * as1[h * 64 + c]);
    atomicAdd(&sAd[h], acc0 * ad1[h * 64 + c]);
    __syncthreads();
    if (t < 4) { g_tatt[v * 8 + t] = sAs[t]; g_tatt[v * 8 + 4 + t] = sAd[t]; }
}

// ---------------- init: CSR counts (self loop), pool accumulators, out ----------------
__global__ void k_init(float* out) {
    int i = blockIdx.x * blockDim.x + threadIdx.x;
    if (i < 2 * NNODES) g_cur[i / NNODES][i % NNODES] = 1;
    if (i < 2 * NGRAPH * 128) out[i] = 0.f;
    if (i < 2 * NGRAPH) g_gcnt[i >> 8][i & 255] = 0;
}

// ---------------- CSR build ----------------
__global__ void k_hist(const int* __restrict__ el, const int* __restrict__ er) {
    int side = blockIdx.z;
    const int* edge = side ? er : el;
    int e = blockIdx.x * blockDim.x + threadIdx.x;
    if (e < NEDGES) atomicAdd(&g_cur[side][edge[NEDGES + e]], 1);
}

__global__ void k_scan_a() {
    int side = blockIdx.z;
    __shared__ int sh[256];
    int t = threadIdx.x, i = blockIdx.x * 256 + t;
    int v = (i < NNODES) ? g_cur[side][i] : 0;
    sh[t] = v;
    __syncthreads();
    for (int o = 1; o < 256; o <<= 1) {
        int x = (t >= o) ? sh[t - o] : 0;
        __syncthreads();
        sh[t] += x;
        __syncthreads();
    }
    if (i < NNODES) g_off[side][i] = sh[t] - v;
    if (t == 255) g_bsum[side][blockIdx.x] = sh[255];
}
__global__ void k_scan_b() {   // grid=2, 32 threads: scan 79 block sums
    int side = blockIdx.x, lane = threadIdx.x;
    int v[3]; int s = 0;
#pragma unroll
    for (int j = 0; j < 3; j++) {
        int b = lane * 3 + j;
        v[j] = (b < 79) ? g_bsum[side][b] : 0;
        s += v[j];
    }
    int ps = s;
    for (int o = 1; o < 32; o <<= 1) {
        int u = __shfl_up_sync(0xffffffffu, ps, o);
        if (lane >= o) ps += u;
    }
    int run = ps - s;
#pragma unroll
    for (int j = 0; j < 3; j++) {
        int b = lane * 3 + j;
        if (b < 79) g_bsum[side][b] = run;
        run += v[j];
    }
}
__global__ void k_scan_c() {
    int side = blockIdx.z;
    int i = blockIdx.x * 256 + threadIdx.x;
    if (i < NNODES) {
        int o = g_off[side][i] + g_bsum[side][i >> 8];
        g_off[side][i] = o;
        g_cur[side][i] = o;
    }
    if (i == 0) g_off[side][NNODES] = NEPLUS;
}

__global__ void k_scatter(const int* __restrict__ el, const int* __restrict__ er) {
    int side = blockIdx.z;
    const int* edge = side ? er : el;
    int e = blockIdx.x * blockDim.x + threadIdx.x;
    if (e < NEPLUS) {
        int s, d;
        if (e < NEDGES) { s = edge[e]; d = edge[NEDGES + e]; }
        else            { s = d = e - NEDGES; }
        int p = atomicAdd(&g_cur[side][d], 1);
        g_srcs[side][p] = s;
    }
}

// ---------------- layer-1 "GEMM" via table gather ----------------
__global__ void k_l1gather(const int* __restrict__ xl, const int* __restrict__ xr) {
    int side = blockIdx.z;
    const int* xi = side ? xr : xl;
    int idx = blockIdx.x * blockDim.x + threadIdx.x;
    if (idx >= NNODES * 128) return;
    int n = idx >> 7, q = idx & 127;
    int v = xi[n];
    float4 val = *(const float4*)(g_tab + v * 512 + q * 4);
    if (q < 64) {
        __half2 h0 = __floats2half2_rn(val.x, val.y);
        __half2 h1 = __floats2half2_rn(val.z, val.w);
        uint2 u = make_uint2(*(uint32_t*)&h0, *(uint32_t*)&h1);
        *(uint2*)(&g_xh[side][n * 256 + q * 4]) = u;
    } else {
        *(float4*)(&g_lin[side][n * 256 + (q - 64) * 4]) = val;
    }
    if (q == 0) {
        *(float4*)(&g_as[side][n * 4]) = *(const float4*)(g_tatt + v * 8);
        *(float4*)(&g_ad[side][n * 4]) = *(const float4*)(g_tatt + v * 8 + 4);
    }
}

// ---------------- fp16 tensor-core GEMM, dual output, cp.async double-buffer --------
__device__ __forceinline__ void mma_f16(float* c, const unsigned* a, const unsigned* b) {
    asm volatile(
        "mma.sync.aligned.m16n8k16.row.col.f32.f16.f16.f32 "
        "{%0,%1,%2,%3},{%4,%5,%6,%7},{%8,%9},{%0,%1,%2,%3};"
        : "+f"(c[0]), "+f"(c[1]), "+f"(c[2]), "+f"(c[3])
        : "r"(a[0]), "r"(a[1]), "r"(a[2]), "r"(a[3]),
          "r"(b[0]), "r"(b[1]));
}

#define AS_STRIDE 40    // halves; 80B row stride -> conflict-free ldmatrix
#define BS_STRIDE 136   // halves; 272B row stride -> conflict-free ldmatrix
#define GEMM_SMEM ((2 * 128 * AS_STRIDE + 2 * 32 * BS_STRIDE) * 2)

__global__ __launch_bounds__(256) void gemm_dual(
    const __half* __restrict__ Abase, long sA,
    const __half* __restrict__ B1, __half* __restrict__ C1base, long sC1, int N1,
    const __half* __restrict__ B2, float* __restrict__ C2base, long sC2, int N2,
    int M, int K) {
    extern __shared__ __half smh[];
    __half (*As)[128][AS_STRIDE] = (__half (*)[128][AS_STRIDE])smh;
    __half (*Bs)[32][BS_STRIDE] = (__half (*)[32][BS_STRIDE])(smh + 2 * 128 * AS_STRIDE);

    int side = blockIdx.z;
    const __half* A = Abase + (size_t)side * sA;
    int t1 = N1 >> 7;
    bool ishalf = ((int)blockIdx.x < t1);
    const __half* B; int N, n0;
    __half* Ch = C1base + (size_t)side * sC1;
    float* Cf = C2base + (size_t)side * sC2;
    if (ishalf) { B = B1; N = N1; n0 = blockIdx.x << 7; }
    else        { B = B2; N = N2; n0 = (blockIdx.x - t1) << 7; }

    int tid = threadIdx.x;
    int warp = tid >> 5, lane = tid & 31;
    int m0 = blockIdx.y * 128;
    int wm = (warp >> 2) * 64;
    int wn = (warp & 3) * 32;
    int gid = lane >> 2, tig = lane & 3;

    float c[4][4][4];
#pragma unroll
    for (int i = 0; i < 4; i++)
#pragma unroll
        for (int j = 0; j < 4; j++)
#pragma unroll
            for (int r = 0; r < 4; r++) c[i][j][r] = 0.f;

    auto load_tile = [&](int s, int kk) {
#pragma unroll
        for (int i = 0; i < 2; i++) {
            int cid = tid + 256 * i;
            int row = cid >> 2, coff = (cid & 3) * 8;     // A: 128 rows x 32 halves
            const __half* asrc = A + (size_t)(m0 + row) * K + kk + coff;
            int sz = (m0 + row < M) ? 16 : 0;
            if (!sz) asrc = A;
            CPA(sptr(&As[s][row][coff]), asrc, sz);
            int krow = cid >> 4, noff = (cid & 15) * 8;   // B: 32 rows x 128 halves
            const __half* bsrc = B + (size_t)(kk + krow) * N + n0 + noff;
            CPA(sptr(&Bs[s][krow][noff]), bsrc, 16);
        }
        CP_COMMIT();
    };

    auto compute = [&](int s) {
#pragma unroll
        for (int ks = 0; ks < 2; ks++) {
            unsigned a[4][4], b[4][2];
#pragma unroll
            for (int mi = 0; mi < 4; mi++) {
                uint32_t addr = sptr(&As[s][wm + mi * 16 + (lane & 15)][ks * 16 + (lane >> 4) * 8]);
                asm volatile("ldmatrix.sync.aligned.m8n8.x4.shared.b16 {%0,%1,%2,%3}, [%4];"
                             : "=r"(a[mi][0]), "=r"(a[mi][1]), "=r"(a[mi][2]), "=r"(a[mi][3])
                             : "r"(addr));
            }
#pragma unroll
            for (int ni = 0; ni < 4; ni++) {
                uint32_t addr = sptr(&Bs[s][ks * 16 + (lane & 15)][wn + ni * 8]);
                asm volatile("ldmatrix.sync.aligned.m8n8.x2.trans.shared.b16 {%0,%1}, [%2];"
                             : "=r"(b[ni][0]), "=r"(b[ni][1])
                             : "r"(addr));
            }
#pragma unroll
            for (int mi = 0; mi < 4; mi++)
#pragma unroll
                for (int ni = 0; ni < 4; ni++) mma_f16(c[mi][ni], a[mi], b[ni]);
        }
    };

    int KT = K >> 5;
    load_tile(0, 0);
    for (int kt = 0; kt < KT; kt++) {
        if (kt + 1 < KT) {
            load_tile((kt + 1) & 1, (kt + 1) << 5);
            CP_WAIT1();
        } else {
            CP_WAIT0();
        }
        __syncthreads();
        compute(kt & 1);
        __syncthreads();
    }
#pragma unroll
    for (int mi = 0; mi < 4; mi++) {
#pragma unroll
        for (int ni = 0; ni < 4; ni++) {
            int r0 = m0 + wm + mi * 16 + gid;
            int cc = n0 + wn + ni * 8 + tig * 2;
            if (ishalf) {
                if (r0 < M)
                    *(__half2*)(Ch + (size_t)r0 * N + cc) =
                        __floats2half2_rn(c[mi][ni][0], c[mi][ni][1]);
                if (r0 + 8 < M)
                    *(__half2*)(Ch + (size_t)(r0 + 8) * N + cc) =
                        __floats2half2_rn(c[mi][ni][2], c[mi][ni][3]);
            } else {
                if (r0 < M)
                    *(float2*)(Cf + (size_t)r0 * N + cc) = make_float2(c[mi][ni][0], c[mi][ni][1]);
                if (r0 + 8 < M)
                    *(float2*)(Cf + (size_t)(r0 + 8) * N + cc) = make_float2(c[mi][ni][2], c[mi][ni][3]);
            }
        }
    }
}

// ---------------- attention scores: warp per node, vectorized ----------------
__global__ void k_att(const float* __restrict__ atts, const float* __restrict__ attd, int C) {
    int side = blockIdx.z;
    int gt = blockIdx.x * blockDim.x + threadIdx.x;
    int n = gt >> 5, lane = gt & 31;
    if (n >= NNODES) return;
    int h = lane >> 3;
    int F = C * 4;
    int hpl = F >> 5;                  // halves per lane: 8 or 16
    int col = lane * hpl;
    const __half* xr = g_xh[side] + (size_t)n * F + col;
    int inner = col - h * C;           // offset within head block
    float ss = 0.f, sd = 0.f;
    int nv = F >> 8;                   // uint4 loads per lane: 1 or 2
    for (int v = 0; v < nv; v++) {
        uint4 u = *(const uint4*)(xr + v * 8);
        __half2* hp = (__half2*)&u;
#pragma unroll
        for (int j = 0; j < 4; j++) {
            float2 f = __half22float2(hp[j]);
            int c0 = h * C + inner + v * 8 + j * 2;
            ss += f.x * atts[c0] + f.y * atts[c0 + 1];
            sd += f.x * attd[c0] + f.y * attd[c0 + 1];
        }
    }
#pragma unroll
    for (int o = 4; o; o >>= 1) {
        ss += __shfl_xor_sync(0xffffffffu, ss, o);
        sd += __shfl_xor_sync(0xffffffffu, sd, o);
    }
    if ((lane & 7) == 0) {
        g_as[side][n * 4 + h] = ss;
        g_ad[side][n * 4 + h] = sd;
    }
}

// ---------------- GAT concat: single-pass softmax aggregation (C=64, F=256) ---------
__global__ void k_gat_concat(const float* __restrict__ bias, const float* __restrict__ lbias,
                             int relu_flag) {
    int side = blockIdx.z;
    int gt = blockIdx.x * blockDim.x + threadIdx.x;
    int i = gt >> 5, lane = gt & 31;
    if (i >= NNODES) return;
    int beg = g_off[side][i], end = g_off[side][i + 1];
    float4 ad4 = *(const float4*)(&g_ad[side][(size_t)i * 4]);
    int h = lane >> 3;
    float adh = pick4(ad4, h);
    int col = lane * 8;
    float z = 0.f;
    float a0 = 0.f, a1 = 0.f, a2 = 0.f, a3 = 0.f, a4 = 0.f, a5 = 0.f, a6 = 0.f, a7 = 0.f;
    int s = g_srcs[side][beg];
    for (int e = beg; e < end; e++) {
        int snx = (e + 1 < end) ? g_srcs[side][e + 1] : 0;
        float4 as4 = *(const float4*)(&g_as[side][(size_t)s * 4]);
        uint4 u = *(const uint4*)(g_xh[side] + (size_t)s * 256 + col);
        float w = __expf(fminf(lrelu(pick4(as4, h) + adh), 80.f));
        z += w;
        __half2* hp = (__half2*)&u;
        float2 f0 = __half22float2(hp[0]);
        float2 f1 = __half22float2(hp[1]);
        float2 f2 = __half22float2(hp[2]);
        float2 f3 = __half22float2(hp[3]);
        a0 += w * f0.x; a1 += w * f0.y; a2 += w * f1.x; a3 += w * f1.y;
        a4 += w * f2.x; a5 += w * f2.y; a6 += w * f3.x; a7 += w * f3.y;
        s = snx;
    }
    float inv = 1.f / (z + 1e-16f);
    a0 *= inv; a1 *= inv; a2 *= inv; a3 *= inv;
    a4 *= inv; a5 *= inv; a6 *= inv; a7 *= inv;
    float4 lr0 = *(const float4*)(g_lin[side] + (size_t)i * 256 + col);
    float4 lr1 = *(const float4*)(g_lin[side] + (size_t)i * 256 + col + 4);
    float4 b0 = *(const float4*)(bias + col);
    float4 b1 = *(const float4*)(bias + col + 4);
    float4 lb0 = *(const float4*)(lbias + col);
    float4 lb1 = *(const float4*)(lbias + col + 4);
    float o0x = a0 + b0.x + lr0.x + lb0.x, o0y = a1 + b0.y + lr0.y + lb0.y;
    float o0z = a2 + b0.z + lr0.z + lb0.z, o0w = a3 + b0.w + lr0.w + lb0.w;
    float o1x = a4 + b1.x + lr1.x + lb1.x, o1y = a5 + b1.y + lr1.y + lb1.y;
    float o1z = a6 + b1.z + lr1.z + lb1.z, o1w = a7 + b1.w + lr1.w + lb1.w;
    if (relu_flag) {
        o0x = fmaxf(o0x, 0.f); o0y = fmaxf(o0y, 0.f);
        o0z = fmaxf(o0z, 0.f); o0w = fmaxf(o0w, 0.f);
        o1x = fmaxf(o1x, 0.f); o1y = fmaxf(o1y, 0.f);
        o1z = fmaxf(o1z, 0.f); o1w = fmaxf(o1w, 0.f);
    }
    __half2 h0 = __floats2half2_rn(o0x, o0y);
    __half2 h1 = __floats2half2_rn(o0z, o0w);
    __half2 h2 = __floats2half2_rn(o1x, o1y);
    __half2 h3 = __floats2half2_rn(o1z, o1w);
    uint4 uo = make_uint4(*(uint32_t*)&h0, *(uint32_t*)&h1, *(uint32_t*)&h2, *(uint32_t*)&h3);
    *(uint4*)(&g_feath[side][(size_t)i * 256 + col]) = uo;
}

// ---------------- GAT mean: single-pass softmax aggregation (C=128, F=512->128) -----
__global__ void k_gat_mean(const float* __restrict__ bias, const float* __restrict__ lbias) {
    int side = blockIdx.z;
    int gt = blockIdx.x * blockDim.x + threadIdx.x;
    int i = gt >> 5, lane = gt & 31;
    if (i >= NNODES) return;
    int beg = g_off[side][i], end = g_off[side][i + 1];
    float4 ad4 = *(const float4*)(&g_ad[side][(size_t)i * 4]);
    int h = lane >> 3;
    float adh = pick4(ad4, h);
    int col = lane * 16;
    float z = 0.f;
    float acc[16];
#pragma unroll
    for (int j = 0; j < 16; j++) acc[j] = 0.f;
    int s = g_srcs[side][beg];
    for (int e = beg; e < end; e++) {
        int snx = (e + 1 < end) ? g_srcs[side][e + 1] : 0;
        float4 as4 = *(const float4*)(&g_as[side][(size_t)s * 4]);
        const uint4* xr = (const uint4*)(g_xh[side] + (size_t)s * 512 + col);
        uint4 u0 = xr[0], u1 = xr[1];
        float w = __expf(fminf(lrelu(pick4(as4, h) + adh), 80.f));
        z += w;
        __half2* hp0 = (__half2*)&u0;
        __half2* hp1 = (__half2*)&u1;
#pragma unroll
        for (int j = 0; j < 4; j++) {
            float2 f = __half22float2(hp0[j]);
            acc[j * 2] += w * f.x; acc[j * 2 + 1] += w * f.y;
        }
#pragma unroll
        for (int j = 0; j < 4; j++) {
            float2 f = __half22float2(hp1[j]);
            acc[8 + j * 2] += w * f.x; acc[8 + j * 2 + 1] += w * f.y;
        }
        s = snx;
    }
    float inv = 1.f / (z + 1e-16f);
#pragma unroll
    for (int j = 0; j < 16; j++) acc[j] *= inv;
#pragma unroll
    for (int mask = 8; mask <= 16; mask <<= 1)
#pragma unroll
        for (int j = 0; j < 16; j++)
            acc[j] += __shfl_xor_sync(0xffffffffu, acc[j], mask);
    if (lane < 8) {
        int c0 = lane * 16;
#pragma unroll
        for (int j = 0; j < 4; j++) {
            int c = c0 + j * 4;
            float4 lr = *(const float4*)(g_lin[side] + (size_t)i * 128 + c);
            float4 bb = *(const float4*)(bias + c);
            float4 lb = *(const float4*)(lbias + c);
            float4 o;
            o.x = 0.25f * acc[j * 4 + 0] + bb.x + lr.x + lb.x;
            o.y = 0.25f * acc[j * 4 + 1] + bb.y + lr.y + lb.y;
            o.z = 0.25f * acc[j * 4 + 2] + bb.z + lr.z + lb.z;
            o.w = 0.25f * acc[j * 4 + 3] + bb.w + lr.w + lb.w;
            *(float4*)(g_feat[side] + (size_t)i * 128 + c) = o;
        }
    }
}

// ---------------- global mean pool: run-length accumulation (batch sorted) ----------
#define POOL_NB 64
__global__ void k_pool_sum(const int* __restrict__ bl, const int* __restrict__ br, float* out) {
    int side = blockIdx.z;
    const int* batch = side ? br : bl;
    float* po = out + side * NGRAPH * 128;
    int n0 = blockIdx.x * POOL_NB;
    int c = threadIdx.x & 127;
    int r = threadIdx.x >> 7;
    float acc = 0.f;
    int cur = -1, cnt = 0;
    for (int j = r; j < POOL_NB; j += 2) {
        int n = n0 + j;
        if (n >= NNODES) break;
        int b = batch[n];
        if (b != cur) {
            if (cur >= 0) {
                atomicAdd(&po[cur * 128 + c], acc);
                if (c == 0) atomicAdd(&g_gcnt[side][cur], cnt);
            }
            acc = 0.f; cnt = 0; cur = b;
        }
        acc += g_feat[side][(size_t)n * 128 + c];
        cnt++;
    }
    if (cur >= 0) {
        atomicAdd(&po[cur * 128 + c], acc);
        if (c == 0) atomicAdd(&g_gcnt[side][cur], cnt);
    }
}
__global__ void k_pool_div(float* out) {
    int i = blockIdx.x * blockDim.x + threadIdx.x;
    if (i < 2 * NGRAPH * 128) {
        int side = i >> 15;
        float cnt = (float)g_gcnt[side][(i >> 7) & 255];
        out[i] /= fmaxf(cnt, 1.f);
    }
}

// ---------------- host orchestration ----------------
extern "C" void kernel_launch(void* const* d_in, const int* in_sizes, int n_in,
                              void* d_out, int out_size) {
    const int* x_l     = (const int*)d_in[0];
    const int* edge_l  = (const int*)d_in[1];
    const int* batch_l = (const int*)d_in[2];
    const int* x_r     = (const int*)d_in[3];
    const int* edge_r  = (const int*)d_in[4];
    const int* batch_r = (const int*)d_in[5];
    const float* emb = (const float*)d_in[6];
    const float* W1  = (const float*)d_in[7];  const float* as1 = (const float*)d_in[8];
    const float* ad1 = (const float*)d_in[9];  const float* b1  = (const float*)d_in[10];
    const float* lw1 = (const float*)d_in[11]; const float* lb1 = (const float*)d_in[12];
    const float* W2  = (const float*)d_in[13]; const float* as2 = (const float*)d_in[14];
    const float* ad2 = (const float*)d_in[15]; const float* b2  = (const float*)d_in[16];
    const float* lw2 = (const float*)d_in[17]; const float* lb2 = (const float*)d_in[18];
    const float* W3  = (const float*)d_in[19]; const float* as3 = (const float*)d_in[20];
    const float* ad3 = (const float*)d_in[21]; const float* b3  = (const float*)d_in[22];
    const float* lw3 = (const float*)d_in[23]; const float* lb3 = (const float*)d_in[24];
    float* out = (float*)d_out;

    __half *feath, *xh, *wh;
    float *lin;
    cudaGetSymbolAddress((void**)&feath, g_feath);
    cudaGetSymbolAddress((void**)&xh, g_xh);
    cudaGetSymbolAddress((void**)&lin, g_lin);
    cudaGetSymbolAddress((void**)&wh, g_wh);

    cudaFuncSetAttribute(gemm_dual, cudaFuncAttributeMaxDynamicSharedMemorySize, GEMM_SMEM);

    const int TB = 256;
    const long sFeat = (long)NNODES * 256, sXh = (long)NNODES * 512, sLin = (long)NNODES * 256;
    const int MB = (NNODES + 127) / 128;
    int warp_grid = (NNODES * 32 + TB - 1) / TB;   // warp-per-node kernels

    // precompute + init + CSR (both sides fused)
    k_wconv<<<(NWH + TB - 1) / TB, TB>>>(W2, lw2, W3, lw3);
    k_pre<<<VOCAB, 256>>>(emb, W1, lw1, as1, ad1);
    k_init<<<(2 * NGRAPH * 128 + TB - 1) / TB, TB>>>(out);
    k_hist<<<dim3((NEDGES + TB - 1) / TB, 1, 2), TB>>>(edge_l, edge_r);
    k_scan_a<<<dim3(79, 1, 2), 256>>>();
    k_scan_b<<<2, 32>>>();
    k_scan_c<<<dim3(79, 1, 2), 256>>>();
    k_scatter<<<dim3((NEPLUS + TB - 1) / TB, 1, 2), TB>>>(edge_l, edge_r);

    // Layer 1: table gather replaces GEMM + att
    k_l1gather<<<dim3((NNODES * 128 + TB - 1) / TB, 1, 2), TB>>>(x_l, x_r);
    k_gat_concat<<<dim3(warp_grid, 1, 2), TB>>>(b1, lb1, 1);

    // Layer 2 (256 -> 256)
    gemm_dual<<<dim3(4, MB, 2), 256, GEMM_SMEM>>>(feath, sFeat, wh, xh, sXh, 256,
                                                  wh + 65536, lin, sLin, 256, NNODES, 256);
    k_att<<<dim3(warp_grid, 1, 2), TB>>>(as2, ad2, 64);
    k_gat_concat<<<dim3(warp_grid, 1, 2), TB>>>(b2, lb2, 1);

    // Layer 3 (256 -> 512 xh / 128 lin)
    gemm_dual<<<dim3(5, MB, 2), 256, GEMM_SMEM>>>(feath, sFeat, wh + 131072, xh, sXh, 512,
                                                  wh + 262144, lin, sLin, 128, NNODES, 256);
    k_att<<<dim3(warp_grid, 1, 2), TB>>>(as3, ad3, 128);
    k_gat_mean<<<dim3(warp_grid, 1, 2), TB>>>(b3, lb3);

    // Pool
    k_pool_sum<<<dim3((NNODES + POOL_NB - 1) / POOL_NB, 1, 2), TB>>>(batch_l, batch_r, out);
    k_pool_div<<<(2 * NGRAPH * 128 + TB - 1) / TB, TB>>>(out);
}

// round 9
// speedup vs baseline: 1.0608x; 1.0608x over previous
#include <cuda_runtime.h>
#include <cuda_fp16.h>
#include <cstdint>

#define NNODES 20000
#define NEDGES 320000
#define NEPLUS 340000   // edges + self loops
#define NGRAPH 256
#define VOCAB  128
#define NWH    294912   // fp16 weights: W2(65536) lw2(65536) W3(131072) lw3(32768)

// ---------------- scratch (device globals; no runtime alloc allowed) ----------------
__device__ float  g_feat [2][NNODES * 128];  // layer-3 output (fp32, pooled)
__device__ __half g_feath[2][NNODES * 256];  // concat-layer outputs (GEMM inputs)
__device__ __half g_xh   [2][NNODES * 512];  // fp16 message features
__device__ float  g_lin  [2][NNODES * 256];
__device__ float  g_as   [2][NNODES * 4];
__device__ float  g_ad   [2][NNODES * 4];
__device__ float  g_exp  [2][NEPLUS * 4];    // cached per-edge exp
__device__ int    g_off  [2][NNODES + 1];
__device__ int    g_cur  [2][NNODES];
__device__ int    g_srcs [2][NEPLUS];
__device__ int    g_gcnt [2][NGRAPH];
__device__ int    g_bsum [2][128];
__device__ float  g_tab  [VOCAB * 512];
__device__ float  g_tatt [VOCAB * 8];
__device__ __half g_wh   [NWH];

__device__ __forceinline__ float lrelu(float x) { return x > 0.f ? x : 0.2f * x; }

__device__ __forceinline__ float pick4(float4 v, int h) {
    float r = v.x;
    r = (h == 1) ? v.y : r;
    r = (h == 2) ? v.z : r;
    r = (h == 3) ? v.w : r;
    return r;
}

__device__ __forceinline__ uint32_t sptr(const void* p) {
    return (uint32_t)__cvta_generic_to_shared(p);
}
#define CPA(dst, src, sz) \
    asm volatile("cp.async.cg.shared.global [%0], [%1], 16, %2;" :: "r"(dst), "l"(src), "r"(sz))
#define CP_COMMIT() asm volatile("cp.async.commit_group;" ::: "memory")
#define CP_WAIT1()  asm volatile("cp.async.wait_group 1;" ::: "memory")
#define CP_WAIT0()  asm volatile("cp.async.wait_group 0;" ::: "memory")

// ---------------- weight fp32->fp16 conversion ----------------
__global__ void k_wconv(const float* __restrict__ W2, const float* __restrict__ lw2,
                        const float* __restrict__ W3, const float* __restrict__ lw3) {
    int i = blockIdx.x * blockDim.x + threadIdx.x;
    if (i >= NWH) return;
    float v;
    if (i < 65536)       v = W2[i];
    else if (i < 131072) v = lw2[i - 65536];
    else if (i < 262144) v = W3[i - 131072];
    else                 v = lw3[i - 262144];
    g_wh[i] = __float2half_rn(v);
}

// ---------------- layer-1 precompute: tables over the 128-entry vocab ----------------
__global__ void k_pre(const float* __restrict__ emb, const float* __restrict__ W1,
                      const float* __restrict__ lw1, const float* __restrict__ as1,
                      const float* __restrict__ ad1) {
    __shared__ float er[128];
    __shared__ float sAs[4], sAd[4];
    int v = blockIdx.x, t = threadIdx.x;  // 256 threads
    if (t < 128) er[t] = emb[v * 128 + t];
    if (t < 4) { sAs[t] = 0.f; sAd[t] = 0.f; }
    __syncthreads();
    float acc0 = 0.f, acc1 = 0.f;
    for (int k = 0; k < 128; k++) {
        float e = er[k];
        acc0 += e * W1[k * 256 + t];
        acc1 += e * lw1[k * 256 + t];
    }
    g_tab[v * 512 + t] = acc0;
    g_tab[v * 512 + 256 + t] = acc1;
    int h = t >> 6, c = t & 63;
    atomicAdd(&sAs[h], acc0 * as1[h * 64 + c]);
    atomicAdd(&sAd[h], acc0 * ad1[h * 64 + c]);
    __syncthreads();
    if (t < 4) { g_tatt[v * 8 + t] = sAs[t]; g_tatt[v * 8 + 4 + t] = sAd[t]; }
}

// ---------------- init: CSR counts (self loop), pool accumulators, out ----------------
__global__ void k_init(float* out) {
    int i = blockIdx.x * blockDim.x + threadIdx.x;
    if (i < 2 * NNODES) g_cur[i / NNODES][i % NNODES] = 1;
    if (i < 2 * NGRAPH * 128) out[i] = 0.f;
    if (i < 2 * NGRAPH) g_gcnt[i >> 8][i & 255] = 0;
}

// ---------------- CSR build ----------------
__global__ void k_hist(const int* __restrict__ el, const int* __restrict__ er) {
    int side = blockIdx.z;
    const int* edge = side ? er : el;
    int e = blockIdx.x * blockDim.x + threadIdx.x;
    if (e < NEDGES) atomicAdd(&g_cur[side][edge[NEDGES + e]], 1);
}

__global__ void k_scan_a() {
    int side = blockIdx.z;
    __shared__ int sh[256];
    int t = threadIdx.x, i = blockIdx.x * 256 + t;
    int v = (i < NNODES) ? g_cur[side][i] : 0;
    sh[t] = v;
    __syncthreads();
    for (int o = 1; o < 256; o <<= 1) {
        int x = (t >= o) ? sh[t - o] : 0;
        __syncthreads();
        sh[t] += x;
        __syncthreads();
    }
    if (i < NNODES) g_off[side][i] = sh[t] - v;
    if (t == 255) g_bsum[side][blockIdx.x] = sh[255];
}
__global__ void k_scan_b() {   // grid=2, 32 threads: scan 79 block sums
    int side = blockIdx.x, lane = threadIdx.x;
    int v[3]; int s = 0;
#pragma unroll
    for (int j = 0; j < 3; j++) {
        int b = lane * 3 + j;
        v[j] = (b < 79) ? g_bsum[side][b] : 0;
        s += v[j];
    }
    int ps = s;
    for (int o = 1; o < 32; o <<= 1) {
        int u = __shfl_up_sync(0xffffffffu, ps, o);
        if (lane >= o) ps += u;
    }
    int run = ps - s;
#pragma unroll
    for (int j = 0; j < 3; j++) {
        int b = lane * 3 + j;
        if (b < 79) g_bsum[side][b] = run;
        run += v[j];
    }
}
__global__ void k_scan_c() {
    int side = blockIdx.z;
    int i = blockIdx.x * 256 + threadIdx.x;
    if (i < NNODES) {
        int o = g_off[side][i] + g_bsum[side][i >> 8];
        g_off[side][i] = o;
        g_cur[side][i] = o;
    }
    if (i == 0) g_off[side][NNODES] = NEPLUS;
}

__global__ void k_scatter(const int* __restrict__ el, const int* __restrict__ er) {
    int side = blockIdx.z;
    const int* edge = side ? er : el;
    int e = blockIdx.x * blockDim.x + threadIdx.x;
    if (e < NEPLUS) {
        int s, d;
        if (e < NEDGES) { s = edge[e]; d = edge[NEDGES + e]; }
        else            { s = d = e - NEDGES; }
        int p = atomicAdd(&g_cur[side][d], 1);
        g_srcs[side][p] = s;
    }
}

// ---------------- layer-1 "GEMM" via table gather ----------------
__global__ void k_l1gather(const int* __restrict__ xl, const int* __restrict__ xr) {
    int side = blockIdx.z;
    const int* xi = side ? xr : xl;
    int idx = blockIdx.x * blockDim.x + threadIdx.x;
    if (idx >= NNODES * 128) return;
    int n = idx >> 7, q = idx & 127;
    int v = xi[n];
    float4 val = *(const float4*)(g_tab + v * 512 + q * 4);
    if (q < 64) {
        __half2 h0 = __floats2half2_rn(val.x, val.y);
        __half2 h1 = __floats2half2_rn(val.z, val.w);
        uint2 u = make_uint2(*(uint32_t*)&h0, *(uint32_t*)&h1);
        *(uint2*)(&g_xh[side][n * 256 + q * 4]) = u;
    } else {
        *(float4*)(&g_lin[side][n * 256 + (q - 64) * 4]) = val;
    }
    if (q == 0) {
        *(float4*)(&g_as[side][n * 4]) = *(const float4*)(g_tatt + v * 8);
        *(float4*)(&g_ad[side][n * 4]) = *(const float4*)(g_tatt + v * 8 + 4);
    }
}

// ---------------- fp16 tensor-core GEMM, dual output, cp.async double-buffer --------
__device__ __forceinline__ void mma_f16(float* c, const unsigned* a, const unsigned* b) {
    asm volatile(
        "mma.sync.aligned.m16n8k16.row.col.f32.f16.f16.f32 "
        "{%0,%1,%2,%3},{%4,%5,%6,%7},{%8,%9},{%0,%1,%2,%3};"
        : "+f"(c[0]), "+f"(c[1]), "+f"(c[2]), "+f"(c[3])
        : "r"(a[0]), "r"(a[1]), "r"(a[2]), "r"(a[3]),
          "r"(b[0]), "r"(b[1]));
}

#define AS_STRIDE 40    // halves; 80B row stride -> conflict-free ldmatrix
#define BS_STRIDE 136   // halves; 272B row stride -> conflict-free ldmatrix
#define GEMM_SMEM ((2 * 128 * AS_STRIDE + 2 * 32 * BS_STRIDE) * 2)

__global__ __launch_bounds__(256) void gemm_dual(
    const __half* __restrict__ Abase, long sA,
    const __half* __restrict__ B1, __half* __restrict__ C1base, long sC1, int N1,
    const __half* __restrict__ B2, float* __restrict__ C2base, long sC2, int N2,
    int M, int K) {
    extern __shared__ __half smh[];
    __half (*As)[128][AS_STRIDE] = (__half (*)[128][AS_STRIDE])smh;
    __half (*Bs)[32][BS_STRIDE] = (__half (*)[32][BS_STRIDE])(smh + 2 * 128 * AS_STRIDE);

    int side = blockIdx.z;
    const __half* A = Abase + (size_t)side * sA;
    int t1 = N1 >> 7;
    bool ishalf = ((int)blockIdx.x < t1);
    const __half* B; int N, n0;
    __half* Ch = C1base + (size_t)side * sC1;
    float* Cf = C2base + (size_t)side * sC2;
    if (ishalf) { B = B1; N = N1; n0 = blockIdx.x << 7; }
    else        { B = B2; N = N2; n0 = (blockIdx.x - t1) << 7; }

    int tid = threadIdx.x;
    int warp = tid >> 5, lane = tid & 31;
    int m0 = blockIdx.y * 128;
    int wm = (warp >> 2) * 64;
    int wn = (warp & 3) * 32;
    int gid = lane >> 2, tig = lane & 3;

    float c[4][4][4];
#pragma unroll
    for (int i = 0; i < 4; i++)
#pragma unroll
        for (int j = 0; j < 4; j++)
#pragma unroll
            for (int r = 0; r < 4; r++) c[i][j][r] = 0.f;

    auto load_tile = [&](int s, int kk) {
#pragma unroll
        for (int i = 0; i < 2; i++) {
            int cid = tid + 256 * i;
            int row = cid >> 2, coff = (cid & 3) * 8;     // A: 128 rows x 32 halves
            const __half* asrc = A + (size_t)(m0 + row) * K + kk + coff;
            int sz = (m0 + row < M) ? 16 : 0;
            if (!sz) asrc = A;
            CPA(sptr(&As[s][row][coff]), asrc, sz);
            int krow = cid >> 4, noff = (cid & 15) * 8;   // B: 32 rows x 128 halves
            const __half* bsrc = B + (size_t)(kk + krow) * N + n0 + noff;
            CPA(sptr(&Bs[s][krow][noff]), bsrc, 16);
        }
        CP_COMMIT();
    };

    auto compute = [&](int s) {
#pragma unroll
        for (int ks = 0; ks < 2; ks++) {
            unsigned a[4][4], b[4][2];
#pragma unroll
            for (int mi = 0; mi < 4; mi++) {
                uint32_t addr = sptr(&As[s][wm + mi * 16 + (lane & 15)][ks * 16 + (lane >> 4) * 8]);
                asm volatile("ldmatrix.sync.aligned.m8n8.x4.shared.b16 {%0,%1,%2,%3}, [%4];"
                             : "=r"(a[mi][0]), "=r"(a[mi][1]), "=r"(a[mi][2]), "=r"(a[mi][3])
                             : "r"(addr));
            }
#pragma unroll
            for (int ni = 0; ni < 4; ni++) {
                uint32_t addr = sptr(&Bs[s][ks * 16 + (lane & 15)][wn + ni * 8]);
                asm volatile("ldmatrix.sync.aligned.m8n8.x2.trans.shared.b16 {%0,%1}, [%2];"
                             : "=r"(b[ni][0]), "=r"(b[ni][1])
                             : "r"(addr));
            }
#pragma unroll
            for (int mi = 0; mi < 4; mi++)
#pragma unroll
                for (int ni = 0; ni < 4; ni++) mma_f16(c[mi][ni], a[mi], b[ni]);
        }
    };

    int KT = K >> 5;
    load_tile(0, 0);
    for (int kt = 0; kt < KT; kt++) {
        if (kt + 1 < KT) {
            load_tile((kt + 1) & 1, (kt + 1) << 5);
            CP_WAIT1();
        } else {
            CP_WAIT0();
        }
        __syncthreads();
        compute(kt & 1);
        __syncthreads();
    }
#pragma unroll
    for (int mi = 0; mi < 4; mi++) {
#pragma unroll
        for (int ni = 0; ni < 4; ni++) {
            int r0 = m0 + wm + mi * 16 + gid;
            int cc = n0 + wn + ni * 8 + tig * 2;
            if (ishalf) {
                if (r0 < M)
                    *(__half2*)(Ch + (size_t)r0 * N + cc) =
                        __floats2half2_rn(c[mi][ni][0], c[mi][ni][1]);
                if (r0 + 8 < M)
                    *(__half2*)(Ch + (size_t)(r0 + 8) * N + cc) =
                        __floats2half2_rn(c[mi][ni][2], c[mi][ni][3]);
            } else {
                if (r0 < M)
                    *(float2*)(Cf + (size_t)r0 * N + cc) = make_float2(c[mi][ni][0], c[mi][ni][1]);
                if (r0 + 8 < M)
                    *(float2*)(Cf + (size_t)(r0 + 8) * N + cc) = make_float2(c[mi][ni][2], c[mi][ni][3]);
            }
        }
    }
}

// ---------------- attention scores: warp per node, vectorized ----------------
__global__ void k_att(const float* __restrict__ atts, const float* __restrict__ attd, int C) {
    int side = blockIdx.z;
    int gt = blockIdx.x * blockDim.x + threadIdx.x;
    int n = gt >> 5, lane = gt & 31;
    if (n >= NNODES) return;
    int h = lane >> 3;
    int F = C * 4;
    int hpl = F >> 5;                  // halves per lane: 8 or 16
    int col = lane * hpl;
    const __half* xr = g_xh[side] + (size_t)n * F + col;
    int inner = col - h * C;           // offset within head block
    float ss = 0.f, sd = 0.f;
    int nv = F >> 8;                   // uint4 loads per lane: 1 or 2
    for (int v = 0; v < nv; v++) {
        uint4 u = *(const uint4*)(xr + v * 8);
        __half2* hp = (__half2*)&u;
#pragma unroll
        for (int j = 0; j < 4; j++) {
            float2 f = __half22float2(hp[j]);
            int c0 = h * C + inner + v * 8 + j * 2;
            ss += f.x * atts[c0] + f.y * atts[c0 + 1];
            sd += f.x * attd[c0] + f.y * attd[c0 + 1];
        }
    }
#pragma unroll
    for (int o = 4; o; o >>= 1) {
        ss += __shfl_xor_sync(0xffffffffu, ss, o);
        sd += __shfl_xor_sync(0xffffffffu, sd, o);
    }
    if ((lane & 7) == 0) {
        g_as[side][n * 4 + h] = ss;
        g_ad[side][n * 4 + h] = sd;
    }
}

// ---------------- GAT concat (C=64, F=256): parallel exp pass + serial gather -------
__global__ void k_gat_concat(const float* __restrict__ bias, const float* __restrict__ lbias,
                             int relu_flag) {
    int side = blockIdx.z;
    int gt = blockIdx.x * blockDim.x + threadIdx.x;
    int i = gt >> 5, lane = gt & 31;
    if (i >= NNODES) return;
    int beg = g_off[side][i], end = g_off[side][i + 1];
    float4 ad = *(const float4*)(&g_ad[side][(size_t)i * 4]);
    // pass A: lane-parallel exp + sum (no max pass; logits are O(1), clamp guards)
    float z0 = 0.f, z1 = 0.f, z2 = 0.f, z3 = 0.f;
    for (int e = beg + lane; e < end; e += 32) {
        int s = g_srcs[side][e];
        float4 as = *(const float4*)(&g_as[side][(size_t)s * 4]);
        float e0 = __expf(fminf(lrelu(as.x + ad.x), 80.f));
        float e1 = __expf(fminf(lrelu(as.y + ad.y), 80.f));
        float e2 = __expf(fminf(lrelu(as.z + ad.z), 80.f));
        float e3 = __expf(fminf(lrelu(as.w + ad.w), 80.f));
        *(float4*)(&g_exp[side][(size_t)e * 4]) = make_float4(e0, e1, e2, e3);
        z0 += e0; z1 += e1; z2 += e2; z3 += e3;
    }
    for (int o = 16; o; o >>= 1) {
        z0 += __shfl_xor_sync(0xffffffffu, z0, o);
        z1 += __shfl_xor_sync(0xffffffffu, z1, o);
        z2 += __shfl_xor_sync(0xffffffffu, z2, o);
        z3 += __shfl_xor_sync(0xffffffffu, z3, o);
    }
    int h = lane >> 3;
    float4 z4 = make_float4(z0, z1, z2, z3);
    float inv = 1.f / (pick4(z4, h) + 1e-16f);
    int col = lane * 8;
    // pass B: warp-serial gather, unrolled x2 for MLP
    float a0 = 0.f, a1 = 0.f, a2 = 0.f, a3 = 0.f, a4 = 0.f, a5 = 0.f, a6 = 0.f, a7 = 0.f;
    int e = beg;
    for (; e + 1 < end; e += 2) {
        int s0 = g_srcs[side][e], s1 = g_srcs[side][e + 1];
        float w0 = g_exp[side][(size_t)e * 4 + h];
        float w1 = g_exp[side][(size_t)e * 4 + 4 + h];
        uint4 u0 = *(const uint4*)(g_xh[side] + (size_t)s0 * 256 + col);
        uint4 u1 = *(const uint4*)(g_xh[side] + (size_t)s1 * 256 + col);
        __half2* p0 = (__half2*)&u0;
        __half2* p1 = (__half2*)&u1;
        float2 f0 = __half22float2(p0[0]), g0 = __half22float2(p1[0]);
        float2 f1 = __half22float2(p0[1]), g1 = __half22float2(p1[1]);
        float2 f2 = __half22float2(p0[2]), g2 = __half22float2(p1[2]);
        float2 f3 = __half22float2(p0[3]), g3 = __half22float2(p1[3]);
        a0 += w0 * f0.x + w1 * g0.x; a1 += w0 * f0.y + w1 * g0.y;
        a2 += w0 * f1.x + w1 * g1.x; a3 += w0 * f1.y + w1 * g1.y;
        a4 += w0 * f2.x + w1 * g2.x; a5 += w0 * f2.y + w1 * g2.y;
        a6 += w0 * f3.x + w1 * g3.x; a7 += w0 * f3.y + w1 * g3.y;
    }
    if (e < end) {
        int s0 = g_srcs[side][e];
        float w0 = g_exp[side][(size_t)e * 4 + h];
        uint4 u0 = *(const uint4*)(g_xh[side] + (size_t)s0 * 256 + col);
        __half2* p0 = (__half2*)&u0;
        float2 f0 = __half22float2(p0[0]);
        float2 f1 = __half22float2(p0[1]);
        float2 f2 = __half22float2(p0[2]);
        float2 f3 = __half22float2(p0[3]);
        a0 += w0 * f0.x; a1 += w0 * f0.y; a2 += w0 * f1.x; a3 += w0 * f1.y;
        a4 += w0 * f2.x; a5 += w0 * f2.y; a6 += w0 * f3.x; a7 += w0 * f3.y;
    }
    a0 *= inv; a1 *= inv; a2 *= inv; a3 *= inv;
    a4 *= inv; a5 *= inv; a6 *= inv; a7 *= inv;
    float4 lr0 = *(const float4*)(g_lin[side] + (size_t)i * 256 + col);
    float4 lr1 = *(const float4*)(g_lin[side] + (size_t)i * 256 + col + 4);
    float4 b0 = *(const float4*)(bias + col);
    float4 b1 = *(const float4*)(bias + col + 4);
    float4 lb0 = *(const float4*)(lbias + col);
    float4 lb1 = *(const float4*)(lbias + col + 4);
    float o0x = a0 + b0.x + lr0.x + lb0.x, o0y = a1 + b0.y + lr0.y + lb0.y;
    float o0z = a2 + b0.z + lr0.z + lb0.z, o0w = a3 + b0.w + lr0.w + lb0.w;
    float o1x = a4 + b1.x + lr1.x + lb1.x, o1y = a5 + b1.y + lr1.y + lb1.y;
    float o1z = a6 + b1.z + lr1.z + lb1.z, o1w = a7 + b1.w + lr1.w + lb1.w;
    if (relu_flag) {
        o0x = fmaxf(o0x, 0.f); o0y = fmaxf(o0y, 0.f);
        o0z = fmaxf(o0z, 0.f); o0w = fmaxf(o0w, 0.f);
        o1x = fmaxf(o1x, 0.f); o1y = fmaxf(o1y, 0.f);
        o1z = fmaxf(o1z, 0.f); o1w = fmaxf(o1w, 0.f);
    }
    __half2 h0 = __floats2half2_rn(o0x, o0y);
    __half2 h1 = __floats2half2_rn(o0z, o0w);
    __half2 h2 = __floats2half2_rn(o1x, o1y);
    __half2 h3 = __floats2half2_rn(o1z, o1w);
    uint4 uo = make_uint4(*(uint32_t*)&h0, *(uint32_t*)&h1, *(uint32_t*)&h2, *(uint32_t*)&h3);
    *(uint4*)(&g_feath[side][(size_t)i * 256 + col]) = uo;
}

// ---------------- GAT mean (C=128, F=512->128): parallel exp pass + serial gather ---
__global__ void k_gat_mean(const float* __restrict__ bias, const float* __restrict__ lbias) {
    int side = blockIdx.z;
    int gt = blockIdx.x * blockDim.x + threadIdx.x;
    int i = gt >> 5, lane = gt & 31;
    if (i >= NNODES) return;
    int beg = g_off[side][i], end = g_off[side][i + 1];
    float4 ad = *(const float4*)(&g_ad[side][(size_t)i * 4]);
    float z0 = 0.f, z1 = 0.f, z2 = 0.f, z3 = 0.f;
    for (int e = beg + lane; e < end; e += 32) {
        int s = g_srcs[side][e];
        float4 as = *(const float4*)(&g_as[side][(size_t)s * 4]);
        float e0 = __expf(fminf(lrelu(as.x + ad.x), 80.f));
        float e1 = __expf(fminf(lrelu(as.y + ad.y), 80.f));
        float e2 = __expf(fminf(lrelu(as.z + ad.z), 80.f));
        float e3 = __expf(fminf(lrelu(as.w + ad.w), 80.f));
        *(float4*)(&g_exp[side][(size_t)e * 4]) = make_float4(e0, e1, e2, e3);
        z0 += e0; z1 += e1; z2 += e2; z3 += e3;
    }
    for (int o = 16; o; o >>= 1) {
        z0 += __shfl_xor_sync(0xffffffffu, z0, o);
        z1 += __shfl_xor_sync(0xffffffffu, z1, o);
        z2 += __shfl_xor_sync(0xffffffffu, z2, o);
        z3 += __shfl_xor_sync(0xffffffffu, z3, o);
    }
    int h = lane >> 3;
    float4 z4 = make_float4(z0, z1, z2, z3);
    float inv = 1.f / (pick4(z4, h) + 1e-16f);
    int col = lane * 16;
    float acc[16];
#pragma unroll
    for (int j = 0; j < 16; j++) acc[j] = 0.f;
    int e = beg;
    for (; e + 1 < end; e += 2) {
        int s0 = g_srcs[side][e], s1 = g_srcs[side][e + 1];
        float w0 = g_exp[side][(size_t)e * 4 + h];
        float w1 = g_exp[side][(size_t)e * 4 + 4 + h];
        const uint4* x0 = (const uint4*)(g_xh[side] + (size_t)s0 * 512 + col);
        const uint4* x1 = (const uint4*)(g_xh[side] + (size_t)s1 * 512 + col);
        uint4 u0 = x0[0], u1 = x0[1], v0 = x1[0], v1 = x1[1];
        __half2* pu0 = (__half2*)&u0;
        __half2* pu1 = (__half2*)&u1;
        __half2* pv0 = (__half2*)&v0;
        __half2* pv1 = (__half2*)&v1;
#pragma unroll
        for (int j = 0; j < 4; j++) {
            float2 f = __half22float2(pu0[j]);
            float2 g = __half22float2(pv0[j]);
            acc[j * 2]     += w0 * f.x + w1 * g.x;
            acc[j * 2 + 1] += w0 * f.y + w1 * g.y;
        }
#pragma unroll
        for (int j = 0; j < 4; j++) {
            float2 f = __half22float2(pu1[j]);
            float2 g = __half22float2(pv1[j]);
            acc[8 + j * 2]     += w0 * f.x + w1 * g.x;
            acc[8 + j * 2 + 1] += w0 * f.y + w1 * g.y;
        }
    }
    if (e < end) {
        int s0 = g_srcs[side][e];
        float w0 = g_exp[side][(size_t)e * 4 + h];
        const uint4* x0 = (const uint4*)(g_xh[side] + (size_t)s0 * 512 + col);
        uint4 u0 = x0[0], u1 = x0[1];
        __half2* pu0 = (__half2*)&u0;
        __half2* pu1 = (__half2*)&u1;
#pragma unroll
        for (int j = 0; j < 4; j++) {
            float2 f = __half22float2(pu0[j]);
            acc[j * 2] += w0 * f.x; acc[j * 2 + 1] += w0 * f.y;
        }
#pragma unroll
        for (int j = 0; j < 4; j++) {
            float2 f = __half22float2(pu1[j]);
            acc[8 + j * 2] += w0 * f.x; acc[8 + j * 2 + 1] += w0 * f.y;
        }
    }
#pragma unroll
    for (int j = 0; j < 16; j++) acc[j] *= inv;
#pragma unroll
    for (int mask = 8; mask <= 16; mask <<= 1)
#pragma unroll
        for (int j = 0; j < 16; j++)
            acc[j] += __shfl_xor_sync(0xffffffffu, acc[j], mask);
    if (lane < 8) {
        int c0 = lane * 16;
#pragma unroll
        for (int j = 0; j < 4; j++) {
            int c = c0 + j * 4;
            float4 lr = *(const float4*)(g_lin[side] + (size_t)i * 128 + c);
            float4 bb = *(const float4*)(bias + c);
            float4 lb = *(const float4*)(lbias + c);
            float4 o;
            o.x = 0.25f * acc[j * 4 + 0] + bb.x + lr.x + lb.x;
            o.y = 0.25f * acc[j * 4 + 1] + bb.y + lr.y + lb.y;
            o.z = 0.25f * acc[j * 4 + 2] + bb.z + lr.z + lb.z;
            o.w = 0.25f * acc[j * 4 + 3] + bb.w + lr.w + lb.w;
            *(float4*)(g_feat[side] + (size_t)i * 128 + c) = o;
        }
    }
}

// ---------------- global mean pool: run-length accumulation (batch sorted) ----------
#define POOL_NB 64
__global__ void k_pool_sum(const int* __restrict__ bl, const int* __restrict__ br, float* out) {
    int side = blockIdx.z;
    const int* batch = side ? br : bl;
    float* po = out + side * NGRAPH * 128;
    int n0 = blockIdx.x * POOL_NB;
    int c = threadIdx.x & 127;
    int r = threadIdx.x >> 7;
    float acc = 0.f;
    int cur = -1, cnt = 0;
    for (int j = r; j < POOL_NB; j += 2) {
        int n = n0 + j;
        if (n >= NNODES) break;
        int b = batch[n];
        if (b != cur) {
            if (cur >= 0) {
                atomicAdd(&po[cur * 128 + c], acc);
                if (c == 0) atomicAdd(&g_gcnt[side][cur], cnt);
            }
            acc = 0.f; cnt = 0; cur = b;
        }
        acc += g_feat[side][(size_t)n * 128 + c];
        cnt++;
    }
    if (cur >= 0) {
        atomicAdd(&po[cur * 128 + c], acc);
        if (c == 0) atomicAdd(&g_gcnt[side][cur], cnt);
    }
}
__global__ void k_pool_div(float* out) {
    int i = blockIdx.x * blockDim.x + threadIdx.x;
    if (i < 2 * NGRAPH * 128) {
        int side = i >> 15;
        float cnt = (float)g_gcnt[side][(i >> 7) & 255];
        out[i] /= fmaxf(cnt, 1.f);
    }
}

// ---------------- host orchestration ----------------
extern "C" void kernel_launch(void* const* d_in, const int* in_sizes, int n_in,
                              void* d_out, int out_size) {
    const int* x_l     = (const int*)d_in[0];
    const int* edge_l  = (const int*)d_in[1];
    const int* batch_l = (const int*)d_in[2];
    const int* x_r     = (const int*)d_in[3];
    const int* edge_r  = (const int*)d_in[4];
    const int* batch_r = (const int*)d_in[5];
    const float* emb = (const float*)d_in[6];
    const float* W1  = (const float*)d_in[7];  const float* as1 = (const float*)d_in[8];
    const float* ad1 = (const float*)d_in[9];  const float* b1  = (const float*)d_in[10];
    const float* lw1 = (const float*)d_in[11]; const float* lb1 = (const float*)d_in[12];
    const float* W2  = (const float*)d_in[13]; const float* as2 = (const float*)d_in[14];
    const float* ad2 = (const float*)d_in[15]; const float* b2  = (const float*)d_in[16];
    const float* lw2 = (const float*)d_in[17]; const float* lb2 = (const float*)d_in[18];
    const float* W3  = (const float*)d_in[19]; const float* as3 = (const float*)d_in[20];
    const float* ad3 = (const float*)d_in[21]; const float* b3  = (const float*)d_in[22];
    const float* lw3 = (const float*)d_in[23]; const float* lb3 = (const float*)d_in[24];
    float* out = (float*)d_out;

    __half *feath, *xh, *wh;
    float *lin;
    cudaGetSymbolAddress((void**)&feath, g_feath);
    cudaGetSymbolAddress((void**)&xh, g_xh);
    cudaGetSymbolAddress((void**)&lin, g_lin);
    cudaGetSymbolAddress((void**)&wh, g_wh);

    cudaFuncSetAttribute(gemm_dual, cudaFuncAttributeMaxDynamicSharedMemorySize, GEMM_SMEM);

    const int TB = 256;
    const long sFeat = (long)NNODES * 256, sXh = (long)NNODES * 512, sLin = (long)NNODES * 256;
    const int MB = (NNODES + 127) / 128;
    int warp_grid = (NNODES * 32 + TB - 1) / TB;   // warp-per-node kernels

    // precompute + init + CSR (both sides fused)
    k_wconv<<<(NWH + TB - 1) / TB, TB>>>(W2, lw2, W3, lw3);
    k_pre<<<VOCAB, 256>>>(emb, W1, lw1, as1, ad1);
    k_init<<<(2 * NGRAPH * 128 + TB - 1) / TB, TB>>>(out);
    k_hist<<<dim3((NEDGES + TB - 1) / TB, 1, 2), TB>>>(edge_l, edge_r);
    k_scan_a<<<dim3(79, 1, 2), 256>>>();
    k_scan_b<<<2, 32>>>();
    k_scan_c<<<dim3(79, 1, 2), 256>>>();
    k_scatter<<<dim3((NEPLUS + TB - 1) / TB, 1, 2), TB>>>(edge_l, edge_r);

    // Layer 1: table gather replaces GEMM + att
    k_l1gather<<<dim3((NNODES * 128 + TB - 1) / TB, 1, 2), TB>>>(x_l, x_r);
    k_gat_concat<<<dim3(warp_grid, 1, 2), TB>>>(b1, lb1, 1);

    // Layer 2 (256 -> 256)
    gemm_dual<<<dim3(4, MB, 2), 256, GEMM_SMEM>>>(feath, sFeat, wh, xh, sXh, 256,
                                                  wh + 65536, lin, sLin, 256, NNODES, 256);
    k_att<<<dim3(warp_grid, 1, 2), TB>>>(as2, ad2, 64);
    k_gat_concat<<<dim3(warp_grid, 1, 2), TB>>>(b2, lb2, 1);

    // Layer 3 (256 -> 512 xh / 128 lin)
    gemm_dual<<<dim3(5, MB, 2), 256, GEMM_SMEM>>>(feath, sFeat, wh + 131072, xh, sXh, 512,
                                                  wh + 262144, lin, sLin, 128, NNODES, 256);
    k_att<<<dim3(warp_grid, 1, 2), TB>>>(as3, ad3, 128);
    k_gat_mean<<<dim3(warp_grid, 1, 2), TB>>>(b3, lb3);

    // Pool
    k_pool_sum<<<dim3((NNODES + POOL_NB - 1) / POOL_NB, 1, 2), TB>>>(batch_l, batch_r, out);
    k_pool_div<<<(2 * NGRAPH * 128 + TB - 1) / TB, TB>>>(out);
}

// round 10
// speedup vs baseline: 1.1579x; 1.0916x over previous
#include <cuda_runtime.h>
#include <cuda_fp16.h>
#include <cstdint>

#define NNODES 20000
#define NEDGES 320000
#define NEPLUS 340000   // edges + self loops
#define NGRAPH 256
#define VOCAB  128
#define NWH    294912   // fp16 weights: W2(65536) lw2(65536) W3(131072) lw3(32768)

// ---------------- scratch (device globals; no runtime alloc allowed) ----------------
__device__ float  g_feat [2][NNODES * 128];  // layer-3 output (fp32, pooled)
__device__ __half g_feath[2][NNODES * 256];  // concat-layer outputs (GEMM inputs)
__device__ __half g_xh   [2][NNODES * 512];  // fp16 message features
__device__ float  g_lin  [2][NNODES * 256];
__device__ float  g_as   [2][NNODES * 4];
__device__ float  g_ad   [2][NNODES * 4];
__device__ float  g_exp  [2][NEPLUS * 4];    // cached per-edge exp
__device__ int    g_off  [2][NNODES + 1];
__device__ int    g_cur  [2][NNODES];
__device__ int    g_srcs [2][NEPLUS];
__device__ int    g_gcnt [2][NGRAPH];
__device__ int    g_bsum [2][128];
__device__ float  g_tab  [VOCAB * 512];
__device__ float  g_tatt [VOCAB * 8];
__device__ __half g_wh   [NWH];

__device__ __forceinline__ float lrelu(float x) { return x > 0.f ? x : 0.2f * x; }

__device__ __forceinline__ uint32_t sptr(const void* p) {
    return (uint32_t)__cvta_generic_to_shared(p);
}
#define CPA(dst, src, sz) \
    asm volatile("cp.async.cg.shared.global [%0], [%1], 16, %2;" :: "r"(dst), "l"(src), "r"(sz))
#define CP_COMMIT() asm volatile("cp.async.commit_group;" ::: "memory")
#define CP_WAIT1()  asm volatile("cp.async.wait_group 1;" ::: "memory")
#define CP_WAIT0()  asm volatile("cp.async.wait_group 0;" ::: "memory")

// ---------------- weight fp32->fp16 conversion ----------------
__global__ void k_wconv(const float* __restrict__ W2, const float* __restrict__ lw2,
                        const float* __restrict__ W3, const float* __restrict__ lw3) {
    int i = blockIdx.x * blockDim.x + threadIdx.x;
    if (i >= NWH) return;
    float v;
    if (i < 65536)       v = W2[i];
    else if (i < 131072) v = lw2[i - 65536];
    else if (i < 262144) v = W3[i - 131072];
    else                 v = lw3[i - 262144];
    g_wh[i] = __float2half_rn(v);
}

// ---------------- layer-1 precompute: tables over the 128-entry vocab ----------------
__global__ void k_pre(const float* __restrict__ emb, const float* __restrict__ W1,
                      const float* __restrict__ lw1, const float* __restrict__ as1,
                      const float* __restrict__ ad1) {
    __shared__ float er[128];
    __shared__ float sAs[4], sAd[4];
    int v = blockIdx.x, t = threadIdx.x;  // 256 threads
    if (t < 128) er[t] = emb[v * 128 + t];
    if (t < 4) { sAs[t] = 0.f; sAd[t] = 0.f; }
    __syncthreads();
    float acc0 = 0.f, acc1 = 0.f;
    for (int k = 0; k < 128; k++) {
        float e = er[k];
        acc0 += e * W1[k * 256 + t];
        acc1 += e * lw1[k * 256 + t];
    }
    g_tab[v * 512 + t] = acc0;
    g_tab[v * 512 + 256 + t] = acc1;
    int h = t >> 6, c = t & 63;
    atomicAdd(&sAs[h], acc0 * as1[h * 64 + c]);
    atomicAdd(&sAd[h], acc0 * ad1[h * 64 + c]);
    __syncthreads();
    if (t < 4) { g_tatt[v * 8 + t] = sAs[t]; g_tatt[v * 8 + 4 + t] = sAd[t]; }
}

// ---------------- init: CSR counts (self loop), pool accumulators, out ----------------
__global__ void k_init(float* out) {
    int i = blockIdx.x * blockDim.x + threadIdx.x;
    if (i < 2 * NNODES) g_cur[i / NNODES][i % NNODES] = 1;
    if (i < 2 * NGRAPH * 128) out[i] = 0.f;
    if (i < 2 * NGRAPH) g_gcnt[i >> 8][i & 255] = 0;
}

// ---------------- CSR build ----------------
__global__ void k_hist(const int* __restrict__ el, const int* __restrict__ er) {
    int side = blockIdx.z;
    const int* edge = side ? er : el;
    int e = blockIdx.x * blockDim.x + threadIdx.x;
    if (e < NEDGES) atomicAdd(&g_cur[side][edge[NEDGES + e]], 1);
}

__global__ void k_scan_a() {
    int side = blockIdx.z;
    __shared__ int sh[256];
    int t = threadIdx.x, i = blockIdx.x * 256 + t;
    int v = (i < NNODES) ? g_cur[side][i] : 0;
    sh[t] = v;
    __syncthreads();
    for (int o = 1; o < 256; o <<= 1) {
        int x = (t >= o) ? sh[t - o] : 0;
        __syncthreads();
        sh[t] += x;
        __syncthreads();
    }
    if (i < NNODES) g_off[side][i] = sh[t] - v;
    if (t == 255) g_bsum[side][blockIdx.x] = sh[255];
}
__global__ void k_scan_b() {   // grid=2, 32 threads: scan 79 block sums
    int side = blockIdx.x, lane = threadIdx.x;
    int v[3]; int s = 0;
#pragma unroll
    for (int j = 0; j < 3; j++) {
        int b = lane * 3 + j;
        v[j] = (b < 79) ? g_bsum[side][b] : 0;
        s += v[j];
    }
    int ps = s;
    for (int o = 1; o < 32; o <<= 1) {
        int u = __shfl_up_sync(0xffffffffu, ps, o);
        if (lane >= o) ps += u;
    }
    int run = ps - s;
#pragma unroll
    for (int j = 0; j < 3; j++) {
        int b = lane * 3 + j;
        if (b < 79) g_bsum[side][b] = run;
        run += v[j];
    }
}
__global__ void k_scan_c() {
    int side = blockIdx.z;
    int i = blockIdx.x * 256 + threadIdx.x;
    if (i < NNODES) {
        int o = g_off[side][i] + g_bsum[side][i >> 8];
        g_off[side][i] = o;
        g_cur[side][i] = o;
    }
    if (i == 0) g_off[side][NNODES] = NEPLUS;
}

__global__ void k_scatter(const int* __restrict__ el, const int* __restrict__ er) {
    int side = blockIdx.z;
    const int* edge = side ? er : el;
    int e = blockIdx.x * blockDim.x + threadIdx.x;
    if (e < NEPLUS) {
        int s, d;
        if (e < NEDGES) { s = edge[e]; d = edge[NEDGES + e]; }
        else            { s = d = e - NEDGES; }
        int p = atomicAdd(&g_cur[side][d], 1);
        g_srcs[side][p] = s;
    }
}

// ---------------- layer-1 "GEMM" via table gather ----------------
__global__ void k_l1gather(const int* __restrict__ xl, const int* __restrict__ xr) {
    int side = blockIdx.z;
    const int* xi = side ? xr : xl;
    int idx = blockIdx.x * blockDim.x + threadIdx.x;
    if (idx >= NNODES * 128) return;
    int n = idx >> 7, q = idx & 127;
    int v = xi[n];
    float4 val = *(const float4*)(g_tab + v * 512 + q * 4);
    if (q < 64) {
        __half2 h0 = __floats2half2_rn(val.x, val.y);
        __half2 h1 = __floats2half2_rn(val.z, val.w);
        uint2 u = make_uint2(*(uint32_t*)&h0, *(uint32_t*)&h1);
        *(uint2*)(&g_xh[side][n * 256 + q * 4]) = u;
    } else {
        *(float4*)(&g_lin[side][n * 256 + (q - 64) * 4]) = val;
    }
    if (q == 0) {
        *(float4*)(&g_as[side][n * 4]) = *(const float4*)(g_tatt + v * 8);
        *(float4*)(&g_ad[side][n * 4]) = *(const float4*)(g_tatt + v * 8 + 4);
    }
}

// ---------------- fp16 tensor-core GEMM, dual output, cp.async double-buffer --------
__device__ __forceinline__ void mma_f16(float* c, const unsigned* a, const unsigned* b) {
    asm volatile(
        "mma.sync.aligned.m16n8k16.row.col.f32.f16.f16.f32 "
        "{%0,%1,%2,%3},{%4,%5,%6,%7},{%8,%9},{%0,%1,%2,%3};"
        : "+f"(c[0]), "+f"(c[1]), "+f"(c[2]), "+f"(c[3])
        : "r"(a[0]), "r"(a[1]), "r"(a[2]), "r"(a[3]),
          "r"(b[0]), "r"(b[1]));
}

#define AS_STRIDE 40    // halves; 80B row stride -> conflict-free ldmatrix
#define BS_STRIDE 136   // halves; 272B row stride -> conflict-free ldmatrix
#define GEMM_SMEM ((2 * 128 * AS_STRIDE + 2 * 32 * BS_STRIDE) * 2)

__global__ __launch_bounds__(256) void gemm_dual(
    const __half* __restrict__ Abase, long sA,
    const __half* __restrict__ B1, __half* __restrict__ C1base, long sC1, int N1,
    const __half* __restrict__ B2, float* __restrict__ C2base, long sC2, int N2,
    int M, int K) {
    extern __shared__ __half smh[];
    __half (*As)[128][AS_STRIDE] = (__half (*)[128][AS_STRIDE])smh;
    __half (*Bs)[32][BS_STRIDE] = (__half (*)[32][BS_STRIDE])(smh + 2 * 128 * AS_STRIDE);

    int side = blockIdx.z;
    const __half* A = Abase + (size_t)side * sA;
    int t1 = N1 >> 7;
    bool ishalf = ((int)blockIdx.x < t1);
    const __half* B; int N, n0;
    __half* Ch = C1base + (size_t)side * sC1;
    float* Cf = C2base + (size_t)side * sC2;
    if (ishalf) { B = B1; N = N1; n0 = blockIdx.x << 7; }
    else        { B = B2; N = N2; n0 = (blockIdx.x - t1) << 7; }

    int tid = threadIdx.x;
    int warp = tid >> 5, lane = tid & 31;
    int m0 = blockIdx.y * 128;
    int wm = (warp >> 2) * 64;
    int wn = (warp & 3) * 32;
    int gid = lane >> 2, tig = lane & 3;

    float c[4][4][4];
#pragma unroll
    for (int i = 0; i < 4; i++)
#pragma unroll
        for (int j = 0; j < 4; j++)
#pragma unroll
            for (int r = 0; r < 4; r++) c[i][j][r] = 0.f;

    auto load_tile = [&](int s, int kk) {
#pragma unroll
        for (int i = 0; i < 2; i++) {
            int cid = tid + 256 * i;
            int row = cid >> 2, coff = (cid & 3) * 8;     // A: 128 rows x 32 halves
            const __half* asrc = A + (size_t)(m0 + row) * K + kk + coff;
            int sz = (m0 + row < M) ? 16 : 0;
            if (!sz) asrc = A;
            CPA(sptr(&As[s][row][coff]), asrc, sz);
            int krow = cid >> 4, noff = (cid & 15) * 8;   // B: 32 rows x 128 halves
            const __half* bsrc = B + (size_t)(kk + krow) * N + n0 + noff;
            CPA(sptr(&Bs[s][krow][noff]), bsrc, 16);
        }
        CP_COMMIT();
    };

    auto compute = [&](int s) {
#pragma unroll
        for (int ks = 0; ks < 2; ks++) {
            unsigned a[4][4], b[4][2];
#pragma unroll
            for (int mi = 0; mi < 4; mi++) {
                uint32_t addr = sptr(&As[s][wm + mi * 16 + (lane & 15)][ks * 16 + (lane >> 4) * 8]);
                asm volatile("ldmatrix.sync.aligned.m8n8.x4.shared.b16 {%0,%1,%2,%3}, [%4];"
                             : "=r"(a[mi][0]), "=r"(a[mi][1]), "=r"(a[mi][2]), "=r"(a[mi][3])
                             : "r"(addr));
            }
#pragma unroll
            for (int ni = 0; ni < 4; ni++) {
                uint32_t addr = sptr(&Bs[s][ks * 16 + (lane & 15)][wn + ni * 8]);
                asm volatile("ldmatrix.sync.aligned.m8n8.x2.trans.shared.b16 {%0,%1}, [%2];"
                             : "=r"(b[ni][0]), "=r"(b[ni][1])
                             : "r"(addr));
            }
#pragma unroll
            for (int mi = 0; mi < 4; mi++)
#pragma unroll
                for (int ni = 0; ni < 4; ni++) mma_f16(c[mi][ni], a[mi], b[ni]);
        }
    };

    int KT = K >> 5;
    load_tile(0, 0);
    for (int kt = 0; kt < KT; kt++) {
        if (kt + 1 < KT) {
            load_tile((kt + 1) & 1, (kt + 1) << 5);
            CP_WAIT1();
        } else {
            CP_WAIT0();
        }
        __syncthreads();
        compute(kt & 1);
        __syncthreads();
    }
#pragma unroll
    for (int mi = 0; mi < 4; mi++) {
#pragma unroll
        for (int ni = 0; ni < 4; ni++) {
            int r0 = m0 + wm + mi * 16 + gid;
            int cc = n0 + wn + ni * 8 + tig * 2;
            if (ishalf) {
                if (r0 < M)
                    *(__half2*)(Ch + (size_t)r0 * N + cc) =
                        __floats2half2_rn(c[mi][ni][0], c[mi][ni][1]);
                if (r0 + 8 < M)
                    *(__half2*)(Ch + (size_t)(r0 + 8) * N + cc) =
                        __floats2half2_rn(c[mi][ni][2], c[mi][ni][3]);
            } else {
                if (r0 < M)
                    *(float2*)(Cf + (size_t)r0 * N + cc) = make_float2(c[mi][ni][0], c[mi][ni][1]);
                if (r0 + 8 < M)
                    *(float2*)(Cf + (size_t)(r0 + 8) * N + cc) = make_float2(c[mi][ni][2], c[mi][ni][3]);
            }
        }
    }
}

// ---------------- attention scores (R7 style: warp per (node,head)) ----------------
__global__ void k_att(const float* __restrict__ atts, const float* __restrict__ attd, int C) {
    int side = blockIdx.z;
    int gt = blockIdx.x * blockDim.x + threadIdx.x;
    int w = gt >> 5, lane = gt & 31;
    if (w >= NNODES * 4) return;
    int n = w >> 2, h = w & 3;
    const __half* xr = g_xh[side] + (size_t)n * 4 * C + h * C;
    float ss = 0.f, sd = 0.f;
    for (int c = lane; c < C; c += 32) {
        float v = __half2float(xr[c]);
        ss += v * atts[h * C + c];
        sd += v * attd[h * C + c];
    }
    for (int o = 16; o; o >>= 1) {
        ss += __shfl_xor_sync(0xffffffffu, ss, o);
        sd += __shfl_xor_sync(0xffffffffu, sd, o);
    }
    if (lane == 0) { g_as[side][n * 4 + h] = ss; g_ad[side][n * 4 + h] = sd; }
}

// ---------------- GAT concat (C=64, F=256): parallel exp pass + serial gather -------
__global__ void k_gat_concat(const float* __restrict__ bias, const float* __restrict__ lbias,
                             int relu_flag) {
    int side = blockIdx.z;
    int gt = blockIdx.x * blockDim.x + threadIdx.x;
    int i = gt >> 5, lane = gt & 31;
    if (i >= NNODES) return;
    int beg = g_off[side][i], end = g_off[side][i + 1];
    float4 ad = *(const float4*)(&g_ad[side][(size_t)i * 4]);
    // pass A: lane-parallel exp + sum (no max pass; logits O(1), clamp guards overflow)
    float z0 = 0.f, z1 = 0.f, z2 = 0.f, z3 = 0.f;
    for (int e = beg + lane; e < end; e += 32) {
        int s = g_srcs[side][e];
        float4 as = *(const float4*)(&g_as[side][(size_t)s * 4]);
        float e0 = __expf(fminf(lrelu(as.x + ad.x), 80.f));
        float e1 = __expf(fminf(lrelu(as.y + ad.y), 80.f));
        float e2 = __expf(fminf(lrelu(as.z + ad.z), 80.f));
        float e3 = __expf(fminf(lrelu(as.w + ad.w), 80.f));
        *(float4*)(&g_exp[side][(size_t)e * 4]) = make_float4(e0, e1, e2, e3);
        z0 += e0; z1 += e1; z2 += e2; z3 += e3;
    }
    for (int o = 16; o; o >>= 1) {
        z0 += __shfl_xor_sync(0xffffffffu, z0, o);
        z1 += __shfl_xor_sync(0xffffffffu, z1, o);
        z2 += __shfl_xor_sync(0xffffffffu, z2, o);
        z3 += __shfl_xor_sync(0xffffffffu, z3, o);
    }
    float i0 = 1.f / (z0 + 1e-16f), i1 = 1.f / (z1 + 1e-16f);
    float i2 = 1.f / (z2 + 1e-16f), i3 = 1.f / (z3 + 1e-16f);
    int h = lane >> 3;
    float myinv = (h == 0) ? i0 : (h == 1) ? i1 : (h == 2) ? i2 : i3;
    int col = lane * 8;   // 8 half columns per lane
    // pass B: warp-serial gather (R7 structure)
    float a0 = 0.f, a1 = 0.f, a2 = 0.f, a3 = 0.f, a4 = 0.f, a5 = 0.f, a6 = 0.f, a7 = 0.f;
    for (int e = beg; e < end; e++) {
        int s = g_srcs[side][e];
        float w = g_exp[side][(size_t)e * 4 + h] * myinv;
        uint4 u = *(const uint4*)(g_xh[side] + (size_t)s * 256 + col);
        __half2* hp = (__half2*)&u;
        float2 f0 = __half22float2(hp[0]);
        float2 f1 = __half22float2(hp[1]);
        float2 f2 = __half22float2(hp[2]);
        float2 f3 = __half22float2(hp[3]);
        a0 += w * f0.x; a1 += w * f0.y; a2 += w * f1.x; a3 += w * f1.y;
        a4 += w * f2.x; a5 += w * f2.y; a6 += w * f3.x; a7 += w * f3.y;
    }
    float4 lr0 = *(const float4*)(g_lin[side] + (size_t)i * 256 + col);
    float4 lr1 = *(const float4*)(g_lin[side] + (size_t)i * 256 + col + 4);
    float4 b0 = *(const float4*)(bias + col);
    float4 b1 = *(const float4*)(bias + col + 4);
    float4 lb0 = *(const float4*)(lbias + col);
    float4 lb1 = *(const float4*)(lbias + col + 4);
    float o0x = a0 + b0.x + lr0.x + lb0.x, o0y = a1 + b0.y + lr0.y + lb0.y;
    float o0z = a2 + b0.z + lr0.z + lb0.z, o0w = a3 + b0.w + lr0.w + lb0.w;
    float o1x = a4 + b1.x + lr1.x + lb1.x, o1y = a5 + b1.y + lr1.y + lb1.y;
    float o1z = a6 + b1.z + lr1.z + lb1.z, o1w = a7 + b1.w + lr1.w + lb1.w;
    if (relu_flag) {
        o0x = fmaxf(o0x, 0.f); o0y = fmaxf(o0y, 0.f);
        o0z = fmaxf(o0z, 0.f); o0w = fmaxf(o0w, 0.f);
        o1x = fmaxf(o1x, 0.f); o1y = fmaxf(o1y, 0.f);
        o1z = fmaxf(o1z, 0.f); o1w = fmaxf(o1w, 0.f);
    }
    __half2 h0 = __floats2half2_rn(o0x, o0y);
    __half2 h1 = __floats2half2_rn(o0z, o0w);
    __half2 h2 = __floats2half2_rn(o1x, o1y);
    __half2 h3 = __floats2half2_rn(o1z, o1w);
    uint4 uo = make_uint4(*(uint32_t*)&h0, *(uint32_t*)&h1, *(uint32_t*)&h2, *(uint32_t*)&h3);
    *(uint4*)(&g_feath[side][(size_t)i * 256 + col]) = uo;
}

// ---------------- GAT mean (C=128, F=512->128): parallel exp pass + serial gather ---
__global__ void k_gat_mean(const float* __restrict__ bias, const float* __restrict__ lbias) {
    int side = blockIdx.z;
    int gt = blockIdx.x * blockDim.x + threadIdx.x;
    int i = gt >> 5, lane = gt & 31;
    if (i >= NNODES) return;
    int beg = g_off[side][i], end = g_off[side][i + 1];
    float4 ad = *(const float4*)(&g_ad[side][(size_t)i * 4]);
    float z0 = 0.f, z1 = 0.f, z2 = 0.f, z3 = 0.f;
    for (int e = beg + lane; e < end; e += 32) {
        int s = g_srcs[side][e];
        float4 as = *(const float4*)(&g_as[side][(size_t)s * 4]);
        float e0 = __expf(fminf(lrelu(as.x + ad.x), 80.f));
        float e1 = __expf(fminf(lrelu(as.y + ad.y), 80.f));
        float e2 = __expf(fminf(lrelu(as.z + ad.z), 80.f));
        float e3 = __expf(fminf(lrelu(as.w + ad.w), 80.f));
        *(float4*)(&g_exp[side][(size_t)e * 4]) = make_float4(e0, e1, e2, e3);
        z0 += e0; z1 += e1; z2 += e2; z3 += e3;
    }
    for (int o = 16; o; o >>= 1) {
        z0 += __shfl_xor_sync(0xffffffffu, z0, o);
        z1 += __shfl_xor_sync(0xffffffffu, z1, o);
        z2 += __shfl_xor_sync(0xffffffffu, z2, o);
        z3 += __shfl_xor_sync(0xffffffffu, z3, o);
    }
    float i0 = 1.f / (z0 + 1e-16f), i1 = 1.f / (z1 + 1e-16f);
    float i2 = 1.f / (z2 + 1e-16f), i3 = 1.f / (z3 + 1e-16f);
    int h = lane >> 3;
    float myinv = (h == 0) ? i0 : (h == 1) ? i1 : (h == 2) ? i2 : i3;
    int col = lane * 16;
    float acc[16];
#pragma unroll
    for (int j = 0; j < 16; j++) acc[j] = 0.f;
    for (int e = beg; e < end; e++) {
        int s = g_srcs[side][e];
        float w = g_exp[side][(size_t)e * 4 + h] * myinv;
        const uint4* xr = (const uint4*)(g_xh[side] + (size_t)s * 512 + col);
        uint4 u0 = xr[0], u1 = xr[1];
        __half2* hp0 = (__half2*)&u0;
        __half2* hp1 = (__half2*)&u1;
#pragma unroll
        for (int j = 0; j < 4; j++) {
            float2 f = __half22float2(hp0[j]);
            acc[j * 2] += w * f.x; acc[j * 2 + 1] += w * f.y;
        }
#pragma unroll
        for (int j = 0; j < 4; j++) {
            float2 f = __half22float2(hp1[j]);
            acc[8 + j * 2] += w * f.x; acc[8 + j * 2 + 1] += w * f.y;
        }
    }
#pragma unroll
    for (int mask = 8; mask <= 16; mask <<= 1)
#pragma unroll
        for (int j = 0; j < 16; j++)
            acc[j] += __shfl_xor_sync(0xffffffffu, acc[j], mask);
    if (lane < 8) {
        int c0 = lane * 16;
#pragma unroll
        for (int j = 0; j < 4; j++) {
            int c = c0 + j * 4;
            float4 lr = *(const float4*)(g_lin[side] + (size_t)i * 128 + c);
            float4 bb = *(const float4*)(bias + c);
            float4 lb = *(const float4*)(lbias + c);
            float4 o;
            o.x = 0.25f * acc[j * 4 + 0] + bb.x + lr.x + lb.x;
            o.y = 0.25f * acc[j * 4 + 1] + bb.y + lr.y + lb.y;
            o.z = 0.25f * acc[j * 4 + 2] + bb.z + lr.z + lb.z;
            o.w = 0.25f * acc[j * 4 + 3] + bb.w + lr.w + lb.w;
            *(float4*)(g_feat[side] + (size_t)i * 128 + c) = o;
        }
    }
}

// ---------------- global mean pool: run-length accumulation (batch sorted) ----------
#define POOL_NB 64
__global__ void k_pool_sum(const int* __restrict__ bl, const int* __restrict__ br, float* out) {
    int side = blockIdx.z;
    const int* batch = side ? br : bl;
    float* po = out + side * NGRAPH * 128;
    int n0 = blockIdx.x * POOL_NB;
    int c = threadIdx.x & 127;
    int r = threadIdx.x >> 7;
    float acc = 0.f;
    int cur = -1, cnt = 0;
    for (int j = r; j < POOL_NB; j += 2) {
        int n = n0 + j;
        if (n >= NNODES) break;
        int b = batch[n];
        if (b != cur) {
            if (cur >= 0) {
                atomicAdd(&po[cur * 128 + c], acc);
                if (c == 0) atomicAdd(&g_gcnt[side][cur], cnt);
            }
            acc = 0.f; cnt = 0; cur = b;
        }
        acc += g_feat[side][(size_t)n * 128 + c];
        cnt++;
    }
    if (cur >= 0) {
        atomicAdd(&po[cur * 128 + c], acc);
        if (c == 0) atomicAdd(&g_gcnt[side][cur], cnt);
    }
}
__global__ void k_pool_div(float* out) {
    int i = blockIdx.x * blockDim.x + threadIdx.x;
    if (i < 2 * NGRAPH * 128) {
        int side = i >> 15;
        float cnt = (float)g_gcnt[side][(i >> 7) & 255];
        out[i] /= fmaxf(cnt, 1.f);
    }
}

// ---------------- host orchestration ----------------
extern "C" void kernel_launch(void* const* d_in, const int* in_sizes, int n_in,
                              void* d_out, int out_size) {
    const int* x_l     = (const int*)d_in[0];
    const int* edge_l  = (const int*)d_in[1];
    const int* batch_l = (const int*)d_in[2];
    const int* x_r     = (const int*)d_in[3];
    const int* edge_r  = (const int*)d_in[4];
    const int* batch_r = (const int*)d_in[5];
    const float* emb = (const float*)d_in[6];
    const float* W1  = (const float*)d_in[7];  const float* as1 = (const float*)d_in[8];
    const float* ad1 = (const float*)d_in[9];  const float* b1  = (const float*)d_in[10];
    const float* lw1 = (const float*)d_in[11]; const float* lb1 = (const float*)d_in[12];
    const float* W2  = (const float*)d_in[13]; const float* as2 = (const float*)d_in[14];
    const float* ad2 = (const float*)d_in[15]; const float* b2  = (const float*)d_in[16];
    const float* lw2 = (const float*)d_in[17]; const float* lb2 = (const float*)d_in[18];
    const float* W3  = (const float*)d_in[19]; const float* as3 = (const float*)d_in[20];
    const float* ad3 = (const float*)d_in[21]; const float* b3  = (const float*)d_in[22];
    const float* lw3 = (const float*)d_in[23]; const float* lb3 = (const float*)d_in[24];
    float* out = (float*)d_out;

    __half *feath, *xh, *wh;
    float *lin;
    cudaGetSymbolAddress((void**)&feath, g_feath);
    cudaGetSymbolAddress((void**)&xh, g_xh);
    cudaGetSymbolAddress((void**)&lin, g_lin);
    cudaGetSymbolAddress((void**)&wh, g_wh);

    cudaFuncSetAttribute(gemm_dual, cudaFuncAttributeMaxDynamicSharedMemorySize, GEMM_SMEM);

    const int TB = 256;
    const long sFeat = (long)NNODES * 256, sXh = (long)NNODES * 512, sLin = (long)NNODES * 256;
    const int MB = (NNODES + 127) / 128;
    int att_grid = (NNODES * 4 * 32 + TB - 1) / TB;   // warp per (node,head)
    int gat_grid = (NNODES * 32 + TB - 1) / TB;       // warp per node

    // precompute + init + CSR (both sides fused)
    k_wconv<<<(NWH + TB - 1) / TB, TB>>>(W2, lw2, W3, lw3);
    k_pre<<<VOCAB, 256>>>(emb, W1, lw1, as1, ad1);
    k_init<<<(2 * NGRAPH * 128 + TB - 1) / TB, TB>>>(out);
    k_hist<<<dim3((NEDGES + TB - 1) / TB, 1, 2), TB>>>(edge_l, edge_r);
    k_scan_a<<<dim3(79, 1, 2), 256>>>();
    k_scan_b<<<2, 32>>>();
    k_scan_c<<<dim3(79, 1, 2), 256>>>();
    k_scatter<<<dim3((NEPLUS + TB - 1) / TB, 1, 2), TB>>>(edge_l, edge_r);

    // Layer 1: table gather replaces GEMM + att
    k_l1gather<<<dim3((NNODES * 128 + TB - 1) / TB, 1, 2), TB>>>(x_l, x_r);
    k_gat_concat<<<dim3(gat_grid, 1, 2), TB>>>(b1, lb1, 1);

    // Layer 2 (256 -> 256)
    gemm_dual<<<dim3(4, MB, 2), 256, GEMM_SMEM>>>(feath, sFeat, wh, xh, sXh, 256,
                                                  wh + 65536, lin, sLin, 256, NNODES, 256);
    k_att<<<dim3(att_grid, 1, 2), TB>>>(as2, ad2, 64);
    k_gat_concat<<<dim3(gat_grid, 1, 2), TB>>>(b2, lb2, 1);

    // Layer 3 (256 -> 512 xh / 128 lin)
    gemm_dual<<<dim3(5, MB, 2), 256, GEMM_SMEM>>>(feath, sFeat, wh + 131072, xh, sXh, 512,
                                                  wh + 262144, lin, sLin, 128, NNODES, 256);
    k_att<<<dim3(att_grid, 1, 2), TB>>>(as3, ad3, 128);
    k_gat_mean<<<dim3(gat_grid, 1, 2), TB>>>(b3, lb3);

    // Pool
    k_pool_sum<<<dim3((NNODES + POOL_NB - 1) / POOL_NB, 1, 2), TB>>>(batch_l, batch_r, out);
    k_pool_div<<<(2 * NGRAPH * 128 + TB - 1) / TB, TB>>>(out);
}